// round 4
// baseline (speedup 1.0000x reference)
#include <cuda_runtime.h>
#include <math.h>

// Problem dims
#define BATCH 256
#define TSTEPS 1024
#define IN_DIM 39
#define HID 256
#define RANK 16

// Scratch: xp = W_in x + b   (B,T,H), and hs = all hidden states (B,T,H)
__device__ float g_xp[BATCH * TSTEPS * HID];
__device__ float g_hs[BATCH * TSTEPS * HID];

// ---------------------------------------------------------------------------
// Kernel 1: input projection. xp[row][i] = b[i] + sum_d W_in[i][d] * x[row][d]
// row = b*T + t (x is (B,T,D) row-major). Block: 256 threads (one per hidden
// unit), each block handles 128 rows. W_in row lives in registers (40 with a
// zero pad); x rows staged in shared and read via broadcast LDS.128.
// ---------------------------------------------------------------------------
__global__ void __launch_bounds__(256) xproj_kernel(
    const float* __restrict__ x,
    const float* __restrict__ W_in,
    const float* __restrict__ bias)
{
    __shared__ float xs[128][40];
    const int i = threadIdx.x;

    float w[40];
#pragma unroll
    for (int d = 0; d < 40; d++)
        w[d] = (d < IN_DIM) ? W_in[i * IN_DIM + d] : 0.f;
    const float bi = bias[i];

    const long row0 = (long)blockIdx.x * 128;

    // stage 128 x-rows into shared (pad col 39 with 0)
    for (int idx = i; idx < 128 * IN_DIM; idx += 256) {
        int rr = idx / IN_DIM;
        int d  = idx - rr * IN_DIM;
        xs[rr][d] = x[row0 * IN_DIM + idx];
    }
    if (i < 128) xs[i][IN_DIM] = 0.f;
    __syncthreads();

#pragma unroll 4
    for (int rr = 0; rr < 128; rr++) {
        const float4* xr = (const float4*)xs[rr];
        float acc = bi;
#pragma unroll
        for (int d4 = 0; d4 < 10; d4++) {
            float4 v = xr[d4];
            acc += w[d4 * 4 + 0] * v.x;
            acc += w[d4 * 4 + 1] * v.y;
            acc += w[d4 * 4 + 2] * v.z;
            acc += w[d4 * 4 + 3] * v.w;
        }
        g_xp[(row0 + rr) * HID + i] = acc;
    }
}

// ---------------------------------------------------------------------------
// Kernel 2: recurrence. 128 CTAs x 512 threads; each CTA owns 2 batch rows
// (one CTA per SM). Thread (bl, i): i = hidden index. Per step:
//   stage1: thread (k = i&15, s = i>>4) computes partial_k_s =
//           sum_{j<16} B_low[k][s*16+j] * h[s*16+j]        (regs x shared h)
//   bar; stage2: threads i<16 reduce 16 slices -> r[k]; bar;
//   stage4: pre = xp[t][i] + sum_k A[i][k]*r[k];  h = tanhf(pre)
//   store h to shared (next step) + global hs; bar.
// xp prefetched one step ahead. 3 barriers / step.
// ---------------------------------------------------------------------------
__global__ void __launch_bounds__(512) recur_kernel(
    const float* __restrict__ A,
    const float* __restrict__ Blow,
    float* __restrict__ hfin)  // points at d_out + B*T*D
{
    __shared__ float h_sh[2][HID];
    __shared__ float part[2][16][16];   // [batch][slice][rank]
    __shared__ float r_sh[2][16];

    const int tid = threadIdx.x;
    const int bl  = tid >> 8;
    const int i   = tid & 255;
    const int b   = blockIdx.x * 2 + bl;
    const int k   = i & 15;
    const int s   = i >> 4;

    // per-thread constant weights
    float bw[16], aw[16];
#pragma unroll
    for (int j = 0; j < 16; j++) bw[j] = Blow[k * HID + s * 16 + j];
#pragma unroll
    for (int j = 0; j < 16; j++) aw[j] = A[i * RANK + j];

    const float* __restrict__ xpb = g_xp + (size_t)b * TSTEPS * HID;
    float*       __restrict__ hsb = g_hs + (size_t)b * TSTEPS * HID;

    float h = 0.f;
    h_sh[bl][i] = 0.f;
    float xp_cur = xpb[i];   // t = 0
    __syncthreads();

#pragma unroll 1
    for (int t = 0; t < TSTEPS; t++) {
        // prefetch next step's xp (off the critical path)
        float xp_nxt = (t + 1 < TSTEPS) ? xpb[(t + 1) * HID + i] : 0.f;

        // --- stage 1: rank-k partial over slice s ---
        const float4* hv = (const float4*)&h_sh[bl][s * 16];
        float p0 = 0.f, p1 = 0.f, p2 = 0.f, p3 = 0.f;
        {
            float4 v0 = hv[0], v1 = hv[1], v2 = hv[2], v3 = hv[3];
            p0 = bw[0] * v0.x + bw[1] * v0.y + bw[2] * v0.z + bw[3] * v0.w;
            p1 = bw[4] * v1.x + bw[5] * v1.y + bw[6] * v1.z + bw[7] * v1.w;
            p2 = bw[8] * v2.x + bw[9] * v2.y + bw[10] * v2.z + bw[11] * v2.w;
            p3 = bw[12] * v3.x + bw[13] * v3.y + bw[14] * v3.z + bw[15] * v3.w;
        }
        part[bl][s][k] = (p0 + p1) + (p2 + p3);
        __syncthreads();

        // --- stage 2: reduce 16 slices -> r[k] ---
        if (i < 16) {
            float r0 = 0.f, r1 = 0.f, r2 = 0.f, r3 = 0.f;
#pragma unroll
            for (int ss = 0; ss < 16; ss += 4) {
                r0 += part[bl][ss + 0][i];
                r1 += part[bl][ss + 1][i];
                r2 += part[bl][ss + 2][i];
                r3 += part[bl][ss + 3][i];
            }
            r_sh[bl][i] = (r0 + r1) + (r2 + r3);
        }
        __syncthreads();

        // --- stage 4: pre = xp + A[i,:] . r ;  h = tanh(pre) ---
        const float4* rv = (const float4*)r_sh[bl];
        float a0, a1, a2, a3;
        {
            float4 v0 = rv[0], v1 = rv[1], v2 = rv[2], v3 = rv[3];
            a0 = aw[0] * v0.x + aw[1] * v0.y + aw[2] * v0.z + aw[3] * v0.w;
            a1 = aw[4] * v1.x + aw[5] * v1.y + aw[6] * v1.z + aw[7] * v1.w;
            a2 = aw[8] * v2.x + aw[9] * v2.y + aw[10] * v2.z + aw[11] * v2.w;
            a3 = aw[12] * v3.x + aw[13] * v3.y + aw[14] * v3.z + aw[15] * v3.w;
        }
        float pre = xp_cur + ((a0 + a1) + (a2 + a3));
        h = tanhf(pre);

        h_sh[bl][i] = h;            // safe: stage-1 reads fenced by bar #1
        hsb[t * HID + i] = h;
        xp_cur = xp_nxt;
        __syncthreads();
    }

    hfin[b * HID + i] = h;
}

// ---------------------------------------------------------------------------
// Kernel 3: decoder. recon[row][d] = b_dec[d] + sum_i W_dec[d][i]*hs[row][i].
// Block 256 threads handles 128 rows x 39 outputs. K-chunked (64) shared
// staging; thread tile 4 rows x 5 cols. Row map r = rt + 32*rr keeps LDS.128
// bank starts {0,4,8,12} (conflict-free with 68-float row pad).
// ---------------------------------------------------------------------------
__global__ void __launch_bounds__(256) decode_kernel(
    const float* __restrict__ Wdec,
    const float* __restrict__ bdec,
    float* __restrict__ out)
{
    __shared__ float ws[40][68];    // W_dec chunk, row padded to 68
    __shared__ float hsm[128][68];  // hs chunk

    const int tid = threadIdx.x;
    const int rt  = tid >> 3;   // 0..31
    const int ct  = tid & 7;    // 0..7
    const long row0 = (long)blockIdx.x * 128;

    float acc[4][5];
#pragma unroll
    for (int rr = 0; rr < 4; rr++)
#pragma unroll
        for (int dd = 0; dd < 5; dd++) acc[rr][dd] = 0.f;

    for (int i0 = 0; i0 < HID; i0 += 64) {
        // stage W_dec chunk (pad row 39 with zeros)
        for (int idx = tid; idx < 40 * 64; idx += 256) {
            int d  = idx >> 6;
            int il = idx & 63;
            ws[d][il] = (d < IN_DIM) ? Wdec[d * HID + i0 + il] : 0.f;
        }
        // stage hs chunk (coalesced float4)
        for (int idx = tid; idx < 128 * 16; idx += 256) {
            int rr = idx >> 4;
            int c4 = idx & 15;
            float4 v = ((const float4*)(g_hs + (row0 + rr) * HID + i0))[c4];
            ((float4*)hsm[rr])[c4] = v;
        }
        __syncthreads();

#pragma unroll
        for (int i4 = 0; i4 < 16; i4++) {
            float4 h4[4], w4[5];
#pragma unroll
            for (int rr = 0; rr < 4; rr++)
                h4[rr] = ((const float4*)hsm[rt + 32 * rr])[i4];
#pragma unroll
            for (int dd = 0; dd < 5; dd++)
                w4[dd] = ((const float4*)ws[ct * 5 + dd])[i4];
#pragma unroll
            for (int rr = 0; rr < 4; rr++)
#pragma unroll
                for (int dd = 0; dd < 5; dd++) {
                    acc[rr][dd] += h4[rr].x * w4[dd].x;
                    acc[rr][dd] += h4[rr].y * w4[dd].y;
                    acc[rr][dd] += h4[rr].z * w4[dd].z;
                    acc[rr][dd] += h4[rr].w * w4[dd].w;
                }
        }
        __syncthreads();
    }

#pragma unroll
    for (int rr = 0; rr < 4; rr++) {
        long row = row0 + rt + 32 * rr;
#pragma unroll
        for (int dd = 0; dd < 5; dd++) {
            int d = ct * 5 + dd;
            if (d < IN_DIM)
                out[row * IN_DIM + d] = acc[rr][dd] + bdec[d];
        }
    }
}

// ---------------------------------------------------------------------------
// Launch: xproj -> recurrence -> decode (default stream, implicit ordering).
// d_in order (metadata): x, W_in, A, B_low, b, W_dec, b_dec
// d_out: recon (B*T*D floats) then h_final (B*H floats)
// ---------------------------------------------------------------------------
extern "C" void kernel_launch(void* const* d_in, const int* in_sizes, int n_in,
                              void* d_out, int out_size)
{
    const float* x     = (const float*)d_in[0];
    const float* W_in  = (const float*)d_in[1];
    const float* A     = (const float*)d_in[2];
    const float* B_low = (const float*)d_in[3];
    const float* bvec  = (const float*)d_in[4];
    const float* W_dec = (const float*)d_in[5];
    const float* b_dec = (const float*)d_in[6];
    float* out = (float*)d_out;

    const int n_rows = BATCH * TSTEPS;            // 262144
    float* hfin = out + (size_t)n_rows * IN_DIM;  // h_final tail

    xproj_kernel<<<n_rows / 128, 256>>>(x, W_in, bvec);
    recur_kernel<<<BATCH / 2, 512>>>(A, B_low, hfin);
    decode_kernel<<<n_rows / 128, 256>>>(W_dec, b_dec, out);
}

// round 5
// speedup vs baseline: 1.0153x; 1.0153x over previous
#include <cuda_runtime.h>
#include <math.h>

// Problem dims
#define BATCH 256
#define TSTEPS 1024
#define IN_DIM 39
#define HID 256
#define RANK 16

// Scratch: xp = W_in x + b   (B,T,H), and hs = all hidden states (B,T,H)
__device__ float g_xp[BATCH * TSTEPS * HID];
__device__ float g_hs[BATCH * TSTEPS * HID];

// ---------------------------------------------------------------------------
// Kernel 1: input projection. xp[row][i] = b[i] + sum_d W_in[i][d] * x[row][d]
// row = b*T + t (x is (B,T,D) row-major). Block: 256 threads (one per hidden
// unit), each block handles 128 rows. W_in row lives in registers (40 with a
// zero pad); x rows staged in shared and read via broadcast LDS.128.
// ---------------------------------------------------------------------------
__global__ void __launch_bounds__(256) xproj_kernel(
    const float* __restrict__ x,
    const float* __restrict__ W_in,
    const float* __restrict__ bias)
{
    __shared__ float xs[128][40];
    const int i = threadIdx.x;

    float w[40];
#pragma unroll
    for (int d = 0; d < 40; d++)
        w[d] = (d < IN_DIM) ? W_in[i * IN_DIM + d] : 0.f;
    const float bi = bias[i];

    const long row0 = (long)blockIdx.x * 128;

    // stage 128 x-rows into shared (pad col 39 with 0)
    for (int idx = i; idx < 128 * IN_DIM; idx += 256) {
        int rr = idx / IN_DIM;
        int d  = idx - rr * IN_DIM;
        xs[rr][d] = x[row0 * IN_DIM + idx];
    }
    if (i < 128) xs[i][IN_DIM] = 0.f;
    __syncthreads();

#pragma unroll 4
    for (int rr = 0; rr < 128; rr++) {
        const float4* xr = (const float4*)xs[rr];
        float acc = bi;
#pragma unroll
        for (int d4 = 0; d4 < 10; d4++) {
            float4 v = xr[d4];
            acc += w[d4 * 4 + 0] * v.x;
            acc += w[d4 * 4 + 1] * v.y;
            acc += w[d4 * 4 + 2] * v.z;
            acc += w[d4 * 4 + 3] * v.w;
        }
        g_xp[(row0 + rr) * HID + i] = acc;
    }
}

// ---------------------------------------------------------------------------
// Kernel 2: recurrence. 128 CTAs x 512 threads; each CTA owns 2 batch rows
// (one CTA per SM). Thread (bl, i): i = hidden index. Per step:
//   stage1: thread (k = i&15, s = i>>4) computes partial_k_s =
//           sum_{j<16} B_low[k][s*16+j] * h[s*16+j]        (regs x shared h)
//   bar; stage2: threads i<16 reduce 16 slices -> r[k]; bar;
//   stage4: pre = xp[t][i] + sum_k A[i][k]*r[k];  h = tanhf(pre)
//   store h to shared (next step) + global hs; bar.
// xp prefetched one step ahead. 3 barriers / step.
// ---------------------------------------------------------------------------
__global__ void __launch_bounds__(512) recur_kernel(
    const float* __restrict__ A,
    const float* __restrict__ Blow,
    float* __restrict__ hfin)  // points at d_out + B*T*D
{
    __shared__ float h_sh[2][HID];
    __shared__ float part[2][16][16];   // [batch][slice][rank]
    __shared__ float r_sh[2][16];

    const int tid = threadIdx.x;
    const int bl  = tid >> 8;
    const int i   = tid & 255;
    const int b   = blockIdx.x * 2 + bl;
    const int k   = i & 15;
    const int s   = i >> 4;

    // per-thread constant weights
    float bw[16], aw[16];
#pragma unroll
    for (int j = 0; j < 16; j++) bw[j] = Blow[k * HID + s * 16 + j];
#pragma unroll
    for (int j = 0; j < 16; j++) aw[j] = A[i * RANK + j];

    const float* __restrict__ xpb = g_xp + (size_t)b * TSTEPS * HID;
    float*       __restrict__ hsb = g_hs + (size_t)b * TSTEPS * HID;

    float h = 0.f;
    h_sh[bl][i] = 0.f;
    float xp_cur = xpb[i];   // t = 0
    __syncthreads();

#pragma unroll 1
    for (int t = 0; t < TSTEPS; t++) {
        // prefetch next step's xp (off the critical path)
        float xp_nxt = (t + 1 < TSTEPS) ? xpb[(t + 1) * HID + i] : 0.f;

        // --- stage 1: rank-k partial over slice s ---
        const float4* hv = (const float4*)&h_sh[bl][s * 16];
        float p0 = 0.f, p1 = 0.f, p2 = 0.f, p3 = 0.f;
        {
            float4 v0 = hv[0], v1 = hv[1], v2 = hv[2], v3 = hv[3];
            p0 = bw[0] * v0.x + bw[1] * v0.y + bw[2] * v0.z + bw[3] * v0.w;
            p1 = bw[4] * v1.x + bw[5] * v1.y + bw[6] * v1.z + bw[7] * v1.w;
            p2 = bw[8] * v2.x + bw[9] * v2.y + bw[10] * v2.z + bw[11] * v2.w;
            p3 = bw[12] * v3.x + bw[13] * v3.y + bw[14] * v3.z + bw[15] * v3.w;
        }
        part[bl][s][k] = (p0 + p1) + (p2 + p3);
        __syncthreads();

        // --- stage 2: reduce 16 slices -> r[k] ---
        if (i < 16) {
            float r0 = 0.f, r1 = 0.f, r2 = 0.f, r3 = 0.f;
#pragma unroll
            for (int ss = 0; ss < 16; ss += 4) {
                r0 += part[bl][ss + 0][i];
                r1 += part[bl][ss + 1][i];
                r2 += part[bl][ss + 2][i];
                r3 += part[bl][ss + 3][i];
            }
            r_sh[bl][i] = (r0 + r1) + (r2 + r3);
        }
        __syncthreads();

        // --- stage 4: pre = xp + A[i,:] . r ;  h = tanh(pre) ---
        const float4* rv = (const float4*)r_sh[bl];
        float a0, a1, a2, a3;
        {
            float4 v0 = rv[0], v1 = rv[1], v2 = rv[2], v3 = rv[3];
            a0 = aw[0] * v0.x + aw[1] * v0.y + aw[2] * v0.z + aw[3] * v0.w;
            a1 = aw[4] * v1.x + aw[5] * v1.y + aw[6] * v1.z + aw[7] * v1.w;
            a2 = aw[8] * v2.x + aw[9] * v2.y + aw[10] * v2.z + aw[11] * v2.w;
            a3 = aw[12] * v3.x + aw[13] * v3.y + aw[14] * v3.z + aw[15] * v3.w;
        }
        float pre = xp_cur + ((a0 + a1) + (a2 + a3));
        h = tanhf(pre);

        h_sh[bl][i] = h;            // safe: stage-1 reads fenced by bar #1
        hsb[t * HID + i] = h;
        xp_cur = xp_nxt;
        __syncthreads();
    }

    hfin[b * HID + i] = h;
}

// ---------------------------------------------------------------------------
// Kernel 3: decoder. recon[row][d] = b_dec[d] + sum_i W_dec[d][i]*hs[row][i].
// Block 256 threads handles 128 rows x 39 outputs. K-chunked (64) shared
// staging; thread tile 4 rows x 5 cols. Row map r = rt + 32*rr keeps LDS.128
// bank starts {0,4,8,12} (conflict-free with 68-float row pad).
// ---------------------------------------------------------------------------
__global__ void __launch_bounds__(256) decode_kernel(
    const float* __restrict__ Wdec,
    const float* __restrict__ bdec,
    float* __restrict__ out)
{
    __shared__ float ws[40][68];    // W_dec chunk, row padded to 68
    __shared__ float hsm[128][68];  // hs chunk

    const int tid = threadIdx.x;
    const int rt  = tid >> 3;   // 0..31
    const int ct  = tid & 7;    // 0..7
    const long row0 = (long)blockIdx.x * 128;

    float acc[4][5];
#pragma unroll
    for (int rr = 0; rr < 4; rr++)
#pragma unroll
        for (int dd = 0; dd < 5; dd++) acc[rr][dd] = 0.f;

    for (int i0 = 0; i0 < HID; i0 += 64) {
        // stage W_dec chunk (pad row 39 with zeros)
        for (int idx = tid; idx < 40 * 64; idx += 256) {
            int d  = idx >> 6;
            int il = idx & 63;
            ws[d][il] = (d < IN_DIM) ? Wdec[d * HID + i0 + il] : 0.f;
        }
        // stage hs chunk (coalesced float4)
        for (int idx = tid; idx < 128 * 16; idx += 256) {
            int rr = idx >> 4;
            int c4 = idx & 15;
            float4 v = ((const float4*)(g_hs + (row0 + rr) * HID + i0))[c4];
            ((float4*)hsm[rr])[c4] = v;
        }
        __syncthreads();

#pragma unroll
        for (int i4 = 0; i4 < 16; i4++) {
            float4 h4[4], w4[5];
#pragma unroll
            for (int rr = 0; rr < 4; rr++)
                h4[rr] = ((const float4*)hsm[rt + 32 * rr])[i4];
#pragma unroll
            for (int dd = 0; dd < 5; dd++)
                w4[dd] = ((const float4*)ws[ct * 5 + dd])[i4];
#pragma unroll
            for (int rr = 0; rr < 4; rr++)
#pragma unroll
                for (int dd = 0; dd < 5; dd++) {
                    acc[rr][dd] += h4[rr].x * w4[dd].x;
                    acc[rr][dd] += h4[rr].y * w4[dd].y;
                    acc[rr][dd] += h4[rr].z * w4[dd].z;
                    acc[rr][dd] += h4[rr].w * w4[dd].w;
                }
        }
        __syncthreads();
    }

#pragma unroll
    for (int rr = 0; rr < 4; rr++) {
        long row = row0 + rt + 32 * rr;
#pragma unroll
        for (int dd = 0; dd < 5; dd++) {
            int d = ct * 5 + dd;
            if (d < IN_DIM)
                out[row * IN_DIM + d] = acc[rr][dd] + bdec[d];
        }
    }
}

// ---------------------------------------------------------------------------
// Launch: xproj -> recurrence -> decode (default stream, implicit ordering).
// d_in order (metadata): x, W_in, A, B_low, b, W_dec, b_dec
// d_out: recon (B*T*D floats) then h_final (B*H floats)
// ---------------------------------------------------------------------------
extern "C" void kernel_launch(void* const* d_in, const int* in_sizes, int n_in,
                              void* d_out, int out_size)
{
    const float* x     = (const float*)d_in[0];
    const float* W_in  = (const float*)d_in[1];
    const float* A     = (const float*)d_in[2];
    const float* B_low = (const float*)d_in[3];
    const float* bvec  = (const float*)d_in[4];
    const float* W_dec = (const float*)d_in[5];
    const float* b_dec = (const float*)d_in[6];
    float* out = (float*)d_out;

    const int n_rows = BATCH * TSTEPS;            // 262144
    float* hfin = out + (size_t)n_rows * IN_DIM;  // h_final tail

    xproj_kernel<<<n_rows / 128, 256>>>(x, W_in, bvec);
    recur_kernel<<<BATCH / 2, 512>>>(A, B_low, hfin);
    decode_kernel<<<n_rows / 128, 256>>>(W_dec, b_dec, out);
}